// round 5
// baseline (speedup 1.0000x reference)
#include <cuda_runtime.h>
#include <math.h>

#define C    2048
#define GRID 148
#define NT   512
#define NWCTA 128          // CTAs doing RNN tile work (128*16 = 2048 rows)

// ---------------- persistent-kernel scratch (device globals; no allocs) ----------------
__device__ __align__(16) float g_inp[C];          // normalized h3 of previous step
__device__ __align__(16) float g_hid[2][4][C];    // double-buffered normalized hidden states
__device__ __align__(16) float g_hraw[3][C];      // raw relu outputs h0..h2 within a step
__device__ __align__(16) float g_lp[2][C];        // LengthProducer hidden activations
__device__ unsigned g_bar;                        // global barrier counter
// Transposed weights: wT[l][k][j] = w[l][j][k]; built once per launch.
__device__ float g_wTih[16777216];                // 4*2048*2048 (64MB)
__device__ float g_wThh[16777216];                // 4*2048*2048 (64MB)

// Near-exact compensated accumulation: TwoProd (FMA) + Kahan, all RN intrinsics.
__device__ __forceinline__ void kacc(float a, float b, float& s, float& cmp, float& es) {
    float p = __fmul_rn(a, b);
    float e = __fmaf_rn(a, b, -p);
    float y = __fsub_rn(p, cmp);
    float t = __fadd_rn(s, y);
    cmp = __fsub_rn(__fsub_rn(t, s), y);
    s = t;
    es = __fadd_rn(es, e);
}
__device__ __forceinline__ void kacc4(float4 a, float4 b, float& s, float& c, float& e) {
    kacc(a.x, b.x, s, c, e); kacc(a.y, b.y, s, c, e);
    kacc(a.z, b.z, s, c, e); kacc(a.w, b.w, s, c, e);
}

// 4B load with L2 cache-hint policy (createpolicy handle).
__device__ __forceinline__ float ldhint(const float* p, unsigned long long pol) {
    float v;
    asm("ld.global.L2::cache_hint.f32 %0, [%1], %2;" : "=f"(v) : "l"(p), "l"(pol));
    return v;
}

// Split grid barrier. All 148 CTAs co-resident.
__device__ __forceinline__ void gbar_arrive() {
    __syncthreads();
    if (threadIdx.x == 0) {
        __threadfence();
        atomicAdd(&g_bar, 1u);
    }
}
__device__ __forceinline__ void gbar_wait(unsigned target) {
    if (threadIdx.x == 0) {
        unsigned v;
        do {
            asm volatile("ld.global.acquire.gpu.u32 %0, [%1];"
                         : "=r"(v) : "l"(&g_bar) : "memory");
        } while (v < target);
    }
    __syncthreads();
}

// ---------------- deterministic active-index compaction ----------------
// 16 warps, warp w scans k in [w*128, w*128+128); ballot/popc keeps ascending order.
__device__ __forceinline__ void build_list(const float* __restrict__ v,
                                           unsigned short* raw, int* cnt,
                                           int wid, int lane) {
    int base = wid * 128;
    int c = 0;
#pragma unroll
    for (int r = 0; r < 4; r++) {
        int k = base + r * 32 + lane;
        bool act = (v[k] != 0.0f);
        unsigned m = __ballot_sync(0xffffffffu, act);
        int pos = __popc(m & ((1u << lane) - 1u));
        if (act) raw[base + c + pos] = (unsigned short)k;
        c += __popc(m);
    }
    if (lane == 0) cnt[wid] = c;
}
// Concatenate the 16 warp segments (caller syncs before and after). off[16] = nnz.
__device__ __forceinline__ void compact_list(const unsigned short* raw, const int* cnt,
                                             unsigned short* dst, int* off,
                                             int wid, int lane, int tid) {
    if (tid == 0) {
        int s = 0;
#pragma unroll
        for (int i = 0; i < 16; i++) { off[i] = s; s += cnt[i]; }
        off[16] = s;
    }
    __syncthreads();
    int o = off[wid], n = cnt[wid];
    for (int i = lane; i < n; i += 32) dst[o + i] = raw[wid * 128 + i];
}

// ---------------- transpose kernel: w[l][j][k] -> wT[l][k][j], 8 matrices ----------------
__global__ void transp_kernel(const float* __restrict__ w_ih, const float* __restrict__ w_hh) {
    __shared__ float tbuf[32][33];
    int m = blockIdx.z;
    const float* src = (m < 4) ? (w_ih + (size_t)m * C * C) : (w_hh + (size_t)(m - 4) * C * C);
    float* dst = (m < 4) ? (g_wTih + (size_t)m * C * C) : (g_wThh + (size_t)(m - 4) * C * C);
    int x = blockIdx.x * 32 + threadIdx.x;          // k
    int y0 = blockIdx.y * 32;                        // j base
#pragma unroll
    for (int r = threadIdx.y; r < 32; r += 8)
        tbuf[r][threadIdx.x] = src[(size_t)(y0 + r) * C + x];
    __syncthreads();
    int xb = blockIdx.x * 32;                        // k base
#pragma unroll
    for (int r = threadIdx.y; r < 32; r += 8)
        dst[(size_t)(xb + r) * C + (y0 + threadIdx.x)] = tbuf[threadIdx.x][r];
}

__global__ void rnn_init(const float* __restrict__ x) {
    int i = blockIdx.x * blockDim.x + threadIdx.x;
    if (i == 0) g_bar = 0u;
    if (i < C) {
        g_inp[i] = 0.f;
        g_hid[0][0][i] = x[i];
        g_hid[0][1][i] = 0.f;
        g_hid[0][2][i] = 0.f;
        g_hid[0][3][i] = 0.f;
    }
}

// LengthProducer dot: dense warp-dot, Kahan + fp64 reduce (one-shot traffic).
__device__ __forceinline__ float dotLP(const float* __restrict__ wrow,
                                       const float* __restrict__ v, int lane) {
    float s = 0.f, c = 0.f, e = 0.f;
    const float4* w4 = reinterpret_cast<const float4*>(wrow);
    const float4* v4 = reinterpret_cast<const float4*>(v);
#pragma unroll
    for (int i = 0; i < 16; i++) {
        float4 a = __ldg(w4 + lane + 32 * i);
        float4 b = v4[lane + 32 * i];
        kacc4(a, b, s, c, e);
    }
    double d = (double)s + (double)c + (double)e;
#pragma unroll
    for (int o = 16; o > 0; o >>= 1)
        d += __shfl_down_sync(0xffffffffu, d, o);
    return (float)d;
}

// Sparse column-gather partial dot: thread handles list entries i = kk, kk+32, ...
// wbase points at wT[l][0][j]; term k contributes wT[l][k][j]*v[k]. 2 Kahan chains.
__device__ __forceinline__ double sparse_dot(const float* __restrict__ wbase,
                                             const unsigned short* __restrict__ lst,
                                             const float* __restrict__ v,
                                             int nnz, int kk, unsigned long long pol) {
    float s0 = 0.f, c0 = 0.f, e0 = 0.f, s1 = 0.f, c1 = 0.f, e1 = 0.f;
    int i = kk;
#pragma unroll 2
    for (; i + 32 < nnz; i += 64) {
        int k0 = lst[i], k1 = lst[i + 32];
        float w0 = ldhint(wbase + (size_t)k0 * C, pol);
        float w1 = ldhint(wbase + (size_t)k1 * C, pol);
        kacc(w0, v[k0], s0, c0, e0);
        kacc(w1, v[k1], s1, c1, e1);
    }
    if (i < nnz) {
        int k0 = lst[i];
        kacc(ldhint(wbase + (size_t)k0 * C, pol), v[k0], s0, c0, e0);
    }
    return ((double)s0 + c0 + e0) + ((double)s1 + c1 + e1);
}

__global__ void __launch_bounds__(NT, 1) rnn_main(
    const float* __restrict__ x,
    const float* __restrict__ lp_w,  const float* __restrict__ lp_b,
    const float* __restrict__ lp_wout, const float* __restrict__ lp_bout,
    const float* __restrict__ b_ih,  const float* __restrict__ b_hh,
    float* __restrict__ out, int T, int has_l)
{
    __shared__ float s_a[C], s_b[C];
    __shared__ unsigned short s_rawA[C], s_rawB[C], s_cA[C], s_cB[C];
    __shared__ int s_cntA[16], s_cntB[16], s_offA[17], s_offB[17], s_nnzB;
    __shared__ double s_redA[NT], s_redB[NT];

    const int tid  = threadIdx.x;
    const int wid  = tid >> 5;
    const int lane = tid & 31;
    const int kk   = tid >> 4;        // 0..31: k-partition lane
    const int jj   = tid & 15;        // 0..15: column within CTA tile
    const int bid  = blockIdx.x;
    const int jlp  = wid * GRID + bid; // LP row mapping (legacy)
    unsigned ph = 0;

    unsigned long long polLast, polFirst;
    asm("createpolicy.fractional.L2::evict_last.b64 %0, 1.0;"  : "=l"(polLast));
    asm("createpolicy.fractional.L2::evict_first.b64 %0, 1.0;" : "=l"(polFirst));

    // ---------------- LengthProducer: 3 hidden Linear + LeakyReLU(0.2) ----------------
    for (int i = 0; i < 3; i++) {
        const float* vin = (i == 0) ? x : g_lp[(i - 1) & 1];
        reinterpret_cast<float4*>(s_a)[tid] = reinterpret_cast<const float4*>(vin)[tid];
        __syncthreads();
        if (jlp < C) {
            float d = dotLP(lp_w + (size_t)i * C * C + (size_t)jlp * C, s_a, lane);
            if (lane == 0) {
                float z = __fadd_rn(d, lp_b[i * C + jlp]);
                g_lp[i & 1][jlp] = (z >= 0.f) ? z : __fmul_rn(0.2f, z);
            }
        }
        gbar_arrive(); ++ph; gbar_wait(ph * GRID);
    }
    // ---------------- LP output scalar ----------------
    if (bid == 0 && wid == 0) {
        float d = dotLP(lp_wout, g_lp[0], lane);
        if (lane == 0 && has_l > 0) {
            float z = __fadd_rn(d, lp_bout[0]);
            out[(size_t)T * C] = fminf(fabsf(z), 0.9999f);
        }
    }
    // tail for first RNN phase: arrive, then stage+list hid[0][0] (=x, dense) pre-wait
    gbar_arrive();
    reinterpret_cast<float4*>(s_b)[tid] = reinterpret_cast<const float4*>(g_hid[0][0])[tid];
    __syncthreads();
    build_list(s_b, s_rawB, s_cntB, wid, lane);
    __syncthreads();
    compact_list(s_rawB, s_cntB, s_cB, s_offB, wid, lane, tid);
    if (tid == 0) s_nnzB = s_offB[16];
    ++ph;

    // ---------------- 4-layer ReLU RNN scan, T steps ----------------
    for (int t = 0; t < T; t++) {
        const int p = t & 1;
#pragma unroll
        for (int l = 0; l < 4; l++) {
            const int nl = (l + 1) & 3;
            const int np = (l == 3) ? (p ^ 1) : p;

            gbar_wait(ph * GRID);          // inputs published; s_b/listB staged pre-wait
            // stage input vector and build its active list
            const float* vin = (l == 0) ? g_inp : g_hraw[l - 1];
            reinterpret_cast<float4*>(s_a)[tid] = reinterpret_cast<const float4*>(vin)[tid];
            __syncthreads();
            build_list(s_a, s_rawA, s_cntA, wid, lane);
            __syncthreads();
            compact_list(s_rawA, s_cntA, s_cA, s_offA, wid, lane, tid);
            __syncthreads();
            const int nnzA = s_offA[16];
            const int nnzB = s_nnzB;

            double da = 0.0, db = 0.0;
            if (bid < NWCTA) {
                const int j = bid * 16 + jj;
                const float* WA = g_wTih + (size_t)l * C * C + j;
                const float* WB = g_wThh + (size_t)l * C * C + j;
                da = sparse_dot(WA, s_cA, s_a, nnzA, kk, polLast);
                db = sparse_dot(WB, s_cB, s_b, nnzB, kk, polFirst);
            }
            // deterministic tree reduction over kk (32 partials per jj)
            s_redA[tid] = da; s_redB[tid] = db;
            __syncthreads();
#pragma unroll
            for (int s = 256; s >= 16; s >>= 1) {
                if (tid < s) {
                    s_redA[tid] += s_redA[tid + s];
                    s_redB[tid] += s_redB[tid + s];
                }
                __syncthreads();
            }
            if (tid < 16 && bid < NWCTA) {
                int j = bid * 16 + tid;
                // ref rounding: ((dih + b_ih) + dhh) + b_hh, all fp32 RN
                float pre = __fadd_rn(__fadd_rn(__fadd_rn((float)s_redA[tid],
                              b_ih[l * C + j]), (float)s_redB[tid]), b_hh[l * C + j]);
                float h  = fmaxf(pre, 0.f);
                float n  = __fsqrt_rn(__fmul_rn(h, h));
                float hn = __fdiv_rn(h, __fadd_rn(n, 1e-12f));
                g_hid[p ^ 1][l][j] = hn;
                if (l < 3) g_hraw[l][j] = h;
                else { g_inp[j] = hn; out[(size_t)t * C + j] = hn; }
            }
            // tail: arrive, then stage + list-build next phase's hid operand (stable)
            gbar_arrive();
            reinterpret_cast<float4*>(s_b)[tid] =
                reinterpret_cast<const float4*>(g_hid[np][nl])[tid];
            __syncthreads();
            build_list(s_b, s_rawB, s_cntB, wid, lane);
            __syncthreads();
            compact_list(s_rawB, s_cntB, s_cB, s_offB, wid, lane, tid);
            if (tid == 0) s_nnzB = s_offB[16];
            ++ph;
        }
    }
}

extern "C" void kernel_launch(void* const* d_in, const int* in_sizes, int n_in,
                              void* d_out, int out_size) {
    const float* x       = (const float*)d_in[0];
    const float* lp_w    = (const float*)d_in[1];
    const float* lp_b    = (const float*)d_in[2];
    const float* lp_wout = (const float*)d_in[3];
    const float* lp_bout = (const float*)d_in[4];
    const float* w_ih    = (const float*)d_in[5];
    const float* b_ih    = (const float*)d_in[6];
    const float* w_hh    = (const float*)d_in[7];
    const float* b_hh    = (const float*)d_in[8];
    float* out = (float*)d_out;

    int T     = out_size / C;        // 512 seq rows
    int has_l = out_size - T * C;    // trailing scalar l present?

    transp_kernel<<<dim3(64, 64, 8), dim3(32, 8)>>>(w_ih, w_hh);
    rnn_init<<<8, 256>>>(x);
    rnn_main<<<GRID, NT>>>(x, lp_w, lp_b, lp_wout, lp_bout,
                           b_ih, b_hh, out, T, has_l);
}

// round 6
// speedup vs baseline: 1.1758x; 1.1758x over previous
#include <cuda_runtime.h>
#include <math.h>

#define C    2048
#define NT   448            // 14 warps, all productive (14*148 = 2072 >= 2048)
#define GRID 148

// ---------------- persistent-kernel scratch (device globals; no allocs) ----------------
__device__ __align__(16) float g_inp[C];          // normalized h3 of previous step (RNN input)
__device__ __align__(16) float g_hid[2][4][C];    // double-buffered normalized hidden states
__device__ __align__(16) float g_hraw[3][C];      // raw relu outputs h0..h2 within a step
__device__ __align__(16) float g_lp[2][C];        // LengthProducer hidden activations
__device__ unsigned g_bar;                        // global barrier counter (reset each launch)

// Near-exact compensated accumulation: TwoProd (FMA) + Kahan, all round-to-nearest intrinsics.
__device__ __forceinline__ void kacc(float a, float b, float& s, float& cmp, float& es) {
    float p = __fmul_rn(a, b);
    float e = __fmaf_rn(a, b, -p);
    float y = __fsub_rn(p, cmp);
    float t = __fadd_rn(s, y);
    cmp = __fsub_rn(__fsub_rn(t, s), y);
    s = t;
    es = __fadd_rn(es, e);
}
__device__ __forceinline__ void kacc4(float4 a, float4 b, float& s, float& c, float& e) {
    kacc(a.x, b.x, s, c, e); kacc(a.y, b.y, s, c, e);
    kacc(a.z, b.z, s, c, e); kacc(a.w, b.w, s, c, e);
}

// 256-bit (8-float) weight chunk. sm_103a requires v4.b64 width for L2 evict hints.
struct F8 { float4 lo, hi; };

__device__ __forceinline__ F8 unpack8(unsigned long long a, unsigned long long b,
                                      unsigned long long c, unsigned long long d) {
    F8 r;
    r.lo.x = __uint_as_float((unsigned)a); r.lo.y = __uint_as_float((unsigned)(a >> 32));
    r.lo.z = __uint_as_float((unsigned)b); r.lo.w = __uint_as_float((unsigned)(b >> 32));
    r.hi.x = __uint_as_float((unsigned)c); r.hi.y = __uint_as_float((unsigned)(c >> 32));
    r.hi.z = __uint_as_float((unsigned)d); r.hi.w = __uint_as_float((unsigned)(d >> 32));
    return r;
}

// POL=0: evict_last (pin ~96MB resident set in L2); POL=1: evict_first (stream 32MB).
template<int POL>
__device__ __forceinline__ F8 ldw8(const F8* p) {
    unsigned long long a, b, c, d;
    if (POL == 0)
        asm("ld.global.nc.L2::evict_last.v4.b64 {%0,%1,%2,%3}, [%4];"
            : "=l"(a), "=l"(b), "=l"(c), "=l"(d) : "l"(p));
    else
        asm("ld.global.nc.L2::evict_first.v4.b64 {%0,%1,%2,%3}, [%4];"
            : "=l"(a), "=l"(b), "=l"(c), "=l"(d) : "l"(p));
    return unpack8(a, b, c, d);
}
// Volatile variant: pinned in program order (issued before the barrier spin) for prefetch.
template<int POL>
__device__ __forceinline__ F8 ldw8v(const F8* p) {
    unsigned long long a, b, c, d;
    if (POL == 0)
        asm volatile("ld.global.nc.L2::evict_last.v4.b64 {%0,%1,%2,%3}, [%4];"
            : "=l"(a), "=l"(b), "=l"(c), "=l"(d) : "l"(p));
    else
        asm volatile("ld.global.nc.L2::evict_first.v4.b64 {%0,%1,%2,%3}, [%4];"
            : "=l"(a), "=l"(b), "=l"(c), "=l"(d) : "l"(p));
    return unpack8(a, b, c, d);
}

// Split grid barrier: arrive (release) / wait (acquire poll). All 148 CTAs co-resident.
__device__ __forceinline__ void gbar_arrive() {
    __syncthreads();
    if (threadIdx.x == 0) {
        __threadfence();
        atomicAdd(&g_bar, 1u);
    }
}
__device__ __forceinline__ void gbar_wait(unsigned target) {
    if (threadIdx.x == 0) {
        unsigned v;
        do {
            asm volatile("ld.global.acquire.gpu.u32 %0, [%1];"
                         : "=r"(v) : "l"(&g_bar) : "memory");
        } while (v < target);
    }
    __syncthreads();
}

__global__ void rnn_init(const float* __restrict__ x) {
    int i = blockIdx.x * blockDim.x + threadIdx.x;
    if (i == 0) g_bar = 0u;
    if (i < C) {
        g_inp[i] = 0.f;
        g_hid[0][0][i] = x[i];
        g_hid[0][1][i] = 0.f;
        g_hid[0][2][i] = 0.f;
        g_hid[0][3][i] = 0.f;
    }
}

// Stage a C-length vector into shared (C/4=512 float4 entries, NT=448 threads).
__device__ __forceinline__ void stage(float* dst, const float* src, int tid) {
    const float4* s4 = reinterpret_cast<const float4*>(src);
    float4* d4 = reinterpret_cast<float4*>(dst);
    d4[tid] = s4[tid];
    if (tid < C / 4 - NT) d4[tid + NT] = s4[tid + NT];
}

// LengthProducer dot: plain 128-bit loads (one-shot traffic), Kahan + fp64 reduce.
__device__ __forceinline__ float dotLP(const float* __restrict__ wrow,
                                       const float* __restrict__ v, int lane) {
    float s = 0.f, c = 0.f, e = 0.f;
    const float4* w4 = reinterpret_cast<const float4*>(wrow);
    const float4* v4 = reinterpret_cast<const float4*>(v);
#pragma unroll
    for (int i = 0; i < 16; i++) {
        float4 a = __ldg(w4 + lane + 32 * i);
        float4 b = v4[lane + 32 * i];
        kacc4(a, b, s, c, e);
    }
    double d = (double)s + (double)c + (double)e;
#pragma unroll
    for (int o = 16; o > 0; o >>= 1)
        d += __shfl_down_sync(0xffffffffu, d, o);
    return (float)d;
}

// Accumulate one F8 weight chunk against two activation float4s into 4 independent
// Kahan chains (component k -> chain k). Cuts the serial dependency path ~4x.
__device__ __forceinline__ void kacc8(const F8& w, float4 alo, float4 ahi,
                                      float* s, float* c, float* e) {
    kacc(w.lo.x, alo.x, s[0], c[0], e[0]);
    kacc(w.lo.y, alo.y, s[1], c[1], e[1]);
    kacc(w.lo.z, alo.z, s[2], c[2], e[2]);
    kacc(w.lo.w, alo.w, s[3], c[3], e[3]);
    kacc(w.hi.x, ahi.x, s[0], c[0], e[0]);
    kacc(w.hi.y, ahi.y, s[1], c[1], e[1]);
    kacc(w.hi.z, ahi.z, s[2], c[2], e[2]);
    kacc(w.hi.w, ahi.w, s[3], c[3], e[3]);
}

// One RNN phase (layer l of step t). PIH/PHH: L2 policy of this phase's weights.
// NIH/NHH: policy of the NEXT phase's weights (chunk-0 prefetched across the barrier).
template<int PIH, int PHH, int NIH, int NHH>
__device__ __forceinline__ void rnn_phase(
    int l, int t, int p, int nl, int np,
    int j, int lane, int tid, unsigned& ph,
    const float* __restrict__ w_ih, const float* __restrict__ w_hh,
    const float* __restrict__ b_ih, const float* __restrict__ b_hh,
    float* __restrict__ out,
    float* s_a, float* s_b,
    F8& A0, F8& A1, F8& B0, F8& B1)
{
    gbar_wait(ph * GRID);                      // this phase's inputs are now published
    const float* vin = (l == 0) ? g_inp : g_hraw[l - 1];
    stage(s_a, vin, tid);
    __syncthreads();

    if (j < C) {
        const F8* wa8 = reinterpret_cast<const F8*>(w_ih + ((size_t)l * C + j) * C);
        const F8* wb8 = reinterpret_cast<const F8*>(w_hh + ((size_t)l * C + j) * C);
        const float4* a4 = reinterpret_cast<const float4*>(s_a);
        const float4* b4 = reinterpret_cast<const float4*>(s_b);
        float sa[4] = {0,0,0,0}, ca[4] = {0,0,0,0}, ea[4] = {0,0,0,0};
        float sb[4] = {0,0,0,0}, cb[4] = {0,0,0,0}, eb[4] = {0,0,0,0};
        F8 x0 = A0, x1 = A1, y0 = B0, y1 = B1;
#pragma unroll
        for (int ch = 0; ch < 4; ch++) {
            F8 n0, n1, m0, m1;
            if (ch < 3) {                       // stream chunk ch+1 while computing chunk ch
                int o = lane + 64 * (ch + 1);
                n0 = ldw8<PIH>(wa8 + o); n1 = ldw8<PIH>(wa8 + o + 32);
                m0 = ldw8<PHH>(wb8 + o); m1 = ldw8<PHH>(wb8 + o + 32);
            }
            int e = lane + 64 * ch;             // float8 slot; float4 indices 2e, 2e+1
            kacc8(x0, a4[2 * e],        a4[2 * e + 1],        sa, ca, ea);
            kacc8(x1, a4[2 * (e + 32)], a4[2 * (e + 32) + 1], sa, ca, ea);
            kacc8(y0, b4[2 * e],        b4[2 * e + 1],        sb, cb, eb);
            kacc8(y1, b4[2 * (e + 32)], b4[2 * (e + 32) + 1], sb, cb, eb);
            if (ch < 3) { x0 = n0; x1 = n1; y0 = m0; y1 = m1; }
        }
        double da = ((double)sa[0] + ca[0] + ea[0]) + ((double)sa[1] + ca[1] + ea[1])
                  + ((double)sa[2] + ca[2] + ea[2]) + ((double)sa[3] + ca[3] + ea[3]);
        double db = ((double)sb[0] + cb[0] + eb[0]) + ((double)sb[1] + cb[1] + eb[1])
                  + ((double)sb[2] + cb[2] + eb[2]) + ((double)sb[3] + cb[3] + eb[3]);
#pragma unroll
        for (int o = 16; o > 0; o >>= 1) {
            da += __shfl_down_sync(0xffffffffu, da, o);
            db += __shfl_down_sync(0xffffffffu, db, o);
        }
        if (lane == 0) {
            // ref rounding: ((dih + b_ih) + dhh) + b_hh, all fp32 RN
            float pre = __fadd_rn(__fadd_rn(__fadd_rn((float)da, b_ih[l * C + j]),
                                            (float)db), b_hh[l * C + j]);
            float h  = fmaxf(pre, 0.f);
            float n  = __fsqrt_rn(__fmul_rn(h, h));
            float hn = __fdiv_rn(h, __fadd_rn(n, 1e-12f));
            g_hid[p ^ 1][l][j] = hn;
            if (l < 3) g_hraw[l][j] = h;
            else { g_inp[j] = hn; out[(size_t)t * C + j] = hn; }
        }
    }

    // ---- tail: prefetch next phase's chunk 0 (overlaps barrier round-trip), arrive, stage s_b ----
    if (j < C) {
        const F8* na = reinterpret_cast<const F8*>(w_ih + ((size_t)nl * C + j) * C);
        const F8* nb = reinterpret_cast<const F8*>(w_hh + ((size_t)nl * C + j) * C);
        A0 = ldw8v<NIH>(na + lane); A1 = ldw8v<NIH>(na + lane + 32);
        B0 = ldw8v<NHH>(nb + lane); B1 = ldw8v<NHH>(nb + lane + 32);
    }
    gbar_arrive();
    // next phase's hid operand has been stable for >=3 barriers: stage pre-wait
    stage(s_b, g_hid[np][nl], tid);
    ++ph;
}

__global__ void __launch_bounds__(NT, 1) rnn_main(
    const float* __restrict__ x,
    const float* __restrict__ lp_w,  const float* __restrict__ lp_b,
    const float* __restrict__ lp_wout, const float* __restrict__ lp_bout,
    const float* __restrict__ w_ih,  const float* __restrict__ b_ih,
    const float* __restrict__ w_hh,  const float* __restrict__ b_hh,
    float* __restrict__ out, int T, int has_l)
{
    __shared__ float s_a[C];
    __shared__ float s_b[C];
    const int tid  = threadIdx.x;
    const int w    = tid >> 5;
    const int lane = tid & 31;
    const int bid  = blockIdx.x;
    const int j    = w * GRID + bid;   // 14 warps * 148 = 2072 rows; j<2048 guard below
    unsigned ph = 0;

    // ---------------- LengthProducer: 3 hidden Linear + LeakyReLU(0.2) ----------------
    for (int i = 0; i < 3; i++) {
        const float* vin = (i == 0) ? x : g_lp[(i - 1) & 1];
        stage(s_a, vin, tid);
        __syncthreads();
        if (j < C) {
            float d = dotLP(lp_w + (size_t)i * C * C + (size_t)j * C, s_a, lane);
            if (lane == 0) {
                float z = __fadd_rn(d, lp_b[i * C + j]);
                g_lp[i & 1][j] = (z >= 0.f) ? z : __fmul_rn(0.2f, z);
            }
        }
        gbar_arrive(); ++ph; gbar_wait(ph * GRID);
    }
    // ---------------- LP output scalar: l = min(|y@wout + bout|, 0.9999) ----------------
    if (bid == 0 && w == 0) {
        float d = dotLP(lp_wout, g_lp[0], lane);
        if (lane == 0 && has_l > 0) {
            float z = __fadd_rn(d, lp_bout[0]);
            out[(size_t)T * C] = fminf(fabsf(z), 0.9999f);
        }
    }
    // prefetch RNN phase (t=0, l=0) chunk 0 and stage its hid operand before arriving
    F8 A0, A1, B0, B1;
    if (j < C) {
        const F8* na = reinterpret_cast<const F8*>(w_ih + (size_t)j * C);
        const F8* nb = reinterpret_cast<const F8*>(w_hh + (size_t)j * C);
        A0 = ldw8v<0>(na + lane); A1 = ldw8v<0>(na + lane + 32);
        B0 = ldw8v<0>(nb + lane); B1 = ldw8v<0>(nb + lane + 32);
    }
    gbar_arrive();
    stage(s_b, g_hid[0][0], tid);
    ++ph;

    // ---------------- 4-layer ReLU RNN scan, T steps ----------------
    // L2 policy map: w_ih all layers pinned (64MB) + w_hh layers 0-1 pinned (32MB) = 96MB
    // evict_last resident set; w_hh layers 2-3 (32MB) streamed evict_first.
    for (int t = 0; t < T; t++) {
        const int p = t & 1;
        rnn_phase<0,0, 0,0>(0, t, p, 1, p,     j, lane, tid, ph, w_ih, w_hh, b_ih, b_hh,
                            out, s_a, s_b, A0, A1, B0, B1);
        rnn_phase<0,0, 0,1>(1, t, p, 2, p,     j, lane, tid, ph, w_ih, w_hh, b_ih, b_hh,
                            out, s_a, s_b, A0, A1, B0, B1);
        rnn_phase<0,1, 0,1>(2, t, p, 3, p,     j, lane, tid, ph, w_ih, w_hh, b_ih, b_hh,
                            out, s_a, s_b, A0, A1, B0, B1);
        rnn_phase<0,1, 0,0>(3, t, p, 0, p ^ 1, j, lane, tid, ph, w_ih, w_hh, b_ih, b_hh,
                            out, s_a, s_b, A0, A1, B0, B1);
    }
}

extern "C" void kernel_launch(void* const* d_in, const int* in_sizes, int n_in,
                              void* d_out, int out_size) {
    const float* x       = (const float*)d_in[0];
    const float* lp_w    = (const float*)d_in[1];
    const float* lp_b    = (const float*)d_in[2];
    const float* lp_wout = (const float*)d_in[3];
    const float* lp_bout = (const float*)d_in[4];
    const float* w_ih    = (const float*)d_in[5];
    const float* b_ih    = (const float*)d_in[6];
    const float* w_hh    = (const float*)d_in[7];
    const float* b_hh    = (const float*)d_in[8];
    float* out = (float*)d_out;

    int T     = out_size / C;        // 512 seq rows
    int has_l = out_size - T * C;    // trailing scalar l present?

    rnn_init<<<8, 256>>>(x);
    rnn_main<<<GRID, NT>>>(x, lp_w, lp_b, lp_wout, lp_bout,
                           w_ih, b_ih, w_hh, b_hh, out, T, has_l);
}

// round 7
// speedup vs baseline: 1.4072x; 1.1969x over previous
#include <cuda_runtime.h>
#include <math.h>

#define C    2048
#define NT   1024           // 32 warps: warp 2r -> ih-dot of row r, warp 2r+1 -> hh-dot
#define GRID 128            // 128 CTAs * 16 rows = 2048

// ---------------- persistent-kernel scratch (device globals; no allocs) ----------------
__device__ __align__(16) float g_inp[C];
__device__ __align__(16) float g_hid[2][4][C];
__device__ __align__(16) float g_hraw[3][C];
__device__ __align__(16) float g_lp[2][C];
__device__ unsigned g_bar;

// Near-exact compensated accumulation: TwoProd (FMA) + Kahan, all RN intrinsics.
__device__ __forceinline__ void kacc(float a, float b, float& s, float& cmp, float& es) {
    float p = __fmul_rn(a, b);
    float e = __fmaf_rn(a, b, -p);
    float y = __fsub_rn(p, cmp);
    float t = __fadd_rn(s, y);
    cmp = __fsub_rn(__fsub_rn(t, s), y);
    s = t;
    es = __fadd_rn(es, e);
}
__device__ __forceinline__ void kacc4(float4 a, float4 b, float& s, float& c, float& e) {
    kacc(a.x, b.x, s, c, e); kacc(a.y, b.y, s, c, e);
    kacc(a.z, b.z, s, c, e); kacc(a.w, b.w, s, c, e);
}

// 256-bit (8-float) weight chunk; sm_103a needs v4.b64 width for L2 evict hints.
struct F8 { float4 lo, hi; };

__device__ __forceinline__ F8 unpack8(unsigned long long a, unsigned long long b,
                                      unsigned long long c, unsigned long long d) {
    F8 r;
    r.lo.x = __uint_as_float((unsigned)a); r.lo.y = __uint_as_float((unsigned)(a >> 32));
    r.lo.z = __uint_as_float((unsigned)b); r.lo.w = __uint_as_float((unsigned)(b >> 32));
    r.hi.x = __uint_as_float((unsigned)c); r.hi.y = __uint_as_float((unsigned)(c >> 32));
    r.hi.z = __uint_as_float((unsigned)d); r.hi.w = __uint_as_float((unsigned)(d >> 32));
    return r;
}

// POL=0: evict_last (pin ~96MB in L2); POL=1: evict_first (stream w_hh[2..3]).
template<int POL>
__device__ __forceinline__ F8 ldw8(const F8* p) {
    unsigned long long a, b, c, d;
    if (POL == 0)
        asm("ld.global.nc.L2::evict_last.v4.b64 {%0,%1,%2,%3}, [%4];"
            : "=l"(a), "=l"(b), "=l"(c), "=l"(d) : "l"(p));
    else
        asm("ld.global.nc.L2::evict_first.v4.b64 {%0,%1,%2,%3}, [%4];"
            : "=l"(a), "=l"(b), "=l"(c), "=l"(d) : "l"(p));
    return unpack8(a, b, c, d);
}
template<int POL>
__device__ __forceinline__ F8 ldw8v(const F8* p) {
    unsigned long long a, b, c, d;
    if (POL == 0)
        asm volatile("ld.global.nc.L2::evict_last.v4.b64 {%0,%1,%2,%3}, [%4];"
            : "=l"(a), "=l"(b), "=l"(c), "=l"(d) : "l"(p));
    else
        asm volatile("ld.global.nc.L2::evict_first.v4.b64 {%0,%1,%2,%3}, [%4];"
            : "=l"(a), "=l"(b), "=l"(c), "=l"(d) : "l"(p));
    return unpack8(a, b, c, d);
}

// Split grid barrier. All 128 CTAs co-resident (1 per SM).
__device__ __forceinline__ void gbar_arrive() {
    __syncthreads();
    if (threadIdx.x == 0) {
        __threadfence();
        atomicAdd(&g_bar, 1u);
    }
}
__device__ __forceinline__ void gbar_wait(unsigned target) {
    if (threadIdx.x == 0) {
        unsigned v;
        do {
            asm volatile("ld.global.acquire.gpu.u32 %0, [%1];"
                         : "=r"(v) : "l"(&g_bar) : "memory");
        } while (v < target);
    }
    __syncthreads();
}

__global__ void rnn_init(const float* __restrict__ x) {
    int i = blockIdx.x * blockDim.x + threadIdx.x;
    if (i == 0) g_bar = 0u;
    if (i < C) {
        g_inp[i] = 0.f;
        g_hid[0][0][i] = x[i];
        g_hid[0][1][i] = 0.f;
        g_hid[0][2][i] = 0.f;
        g_hid[0][3][i] = 0.f;
    }
}

// Stage a C-length vector into shared (512 float4, 1024 threads -> half stage).
__device__ __forceinline__ void stage(float* dst, const float* src, int tid) {
    if (tid < C / 4)
        reinterpret_cast<float4*>(dst)[tid] = reinterpret_cast<const float4*>(src)[tid];
}

// LengthProducer dot: plain loads (one-shot traffic), Kahan + fp64 reduce.
__device__ __forceinline__ float dotLP(const float* __restrict__ wrow,
                                       const float* __restrict__ v, int lane) {
    float s = 0.f, c = 0.f, e = 0.f;
    const float4* w4 = reinterpret_cast<const float4*>(wrow);
    const float4* v4 = reinterpret_cast<const float4*>(v);
#pragma unroll
    for (int i = 0; i < 16; i++) {
        float4 a = __ldg(w4 + lane + 32 * i);
        float4 b = v4[lane + 32 * i];
        kacc4(a, b, s, c, e);
    }
    double d = (double)s + (double)c + (double)e;
#pragma unroll
    for (int o = 16; o > 0; o >>= 1)
        d += __shfl_down_sync(0xffffffffu, d, o);
    return (float)d;
}

// One full-row exact dot per warp: 8 F8 slots/lane (slot = lane+32i), 2 Kahan chains,
// double-buffered pair pipeline (load pair k+1 while computing pair k).
template<int POL>
__device__ __forceinline__ double dot_row(const F8* __restrict__ w8,
                                          const float* __restrict__ v,
                                          int lane, F8 A0, F8 A1) {
    const float4* v4 = reinterpret_cast<const float4*>(v);
    float s0 = 0.f, c0 = 0.f, e0 = 0.f, s1 = 0.f, c1 = 0.f, e1 = 0.f;
    F8 x0 = A0, x1 = A1;
#pragma unroll
    for (int k = 0; k < 4; k++) {
        F8 n0, n1;
        if (k < 3) {
            int o = lane + 64 * (k + 1);
            n0 = ldw8<POL>(w8 + o);
            n1 = ldw8<POL>(w8 + o + 32);
        }
        int t0 = lane + 64 * k, t1 = t0 + 32;
        kacc4(x0.lo, v4[2 * t0],     s0, c0, e0);
        kacc4(x0.hi, v4[2 * t0 + 1], s0, c0, e0);
        kacc4(x1.lo, v4[2 * t1],     s1, c1, e1);
        kacc4(x1.hi, v4[2 * t1 + 1], s1, c1, e1);
        if (k < 3) { x0 = n0; x1 = n1; }
    }
    return ((double)s0 + c0 + e0) + ((double)s1 + c1 + e1);
}

// One RNN phase. PIH/PHH: policies of this phase's ih/hh weights; NIH/NHH: next phase's.
template<int PIH, int PHH, int NIH, int NHH>
__device__ __forceinline__ void rnn_phase(
    int l, int t, int p, int nl, int np,
    int j, int m, int wid, int lane, int tid, unsigned& ph,
    const float* __restrict__ w_ih, const float* __restrict__ w_hh,
    const float* __restrict__ b_ih, const float* __restrict__ b_hh,
    float* __restrict__ out,
    float* s_a, float* s_b, double* s_red,
    F8& A0, F8& A1)
{
    gbar_wait(ph * GRID);                      // inputs published; s_b staged pre-wait
    const float* vin = (l == 0) ? g_inp : g_hraw[l - 1];
    stage(s_a, vin, tid);
    __syncthreads();

    double d;
    if (m == 0)
        d = dot_row<PIH>(reinterpret_cast<const F8*>(w_ih + ((size_t)l * C + j) * C),
                         s_a, lane, A0, A1);
    else
        d = dot_row<PHH>(reinterpret_cast<const F8*>(w_hh + ((size_t)l * C + j) * C),
                         s_b, lane, A0, A1);
#pragma unroll
    for (int o = 16; o > 0; o >>= 1)
        d += __shfl_down_sync(0xffffffffu, d, o);
    if (lane == 0) s_red[wid] = d;
    __syncthreads();

    if (tid < 16) {
        int jj = (blockIdx.x << 4) + tid;
        // ref rounding: ((dih + b_ih) + dhh) + b_hh, all fp32 RN
        float pre = __fadd_rn(__fadd_rn(__fadd_rn((float)s_red[2 * tid],
                        b_ih[l * C + jj]), (float)s_red[2 * tid + 1]), b_hh[l * C + jj]);
        float h  = fmaxf(pre, 0.f);
        float n  = __fsqrt_rn(__fmul_rn(h, h));
        float hn = __fdiv_rn(h, __fadd_rn(n, 1e-12f));
        g_hid[p ^ 1][l][jj] = hn;
        if (l < 3) g_hraw[l][jj] = h;
        else { g_inp[jj] = hn; out[(size_t)t * C + jj] = hn; }
    }

    // ---- tail: prefetch next phase's pair 0 (overlaps barrier), arrive, stage s_b ----
    {
        const F8* nb = reinterpret_cast<const F8*>(
            ((m == 0) ? w_ih : w_hh) + ((size_t)nl * C + j) * C);
        if (m == 0) { A0 = ldw8v<NIH>(nb + lane); A1 = ldw8v<NIH>(nb + lane + 32); }
        else        { A0 = ldw8v<NHH>(nb + lane); A1 = ldw8v<NHH>(nb + lane + 32); }
    }
    gbar_arrive();
    stage(s_b, g_hid[np][nl], tid);            // stable operand (published >=3 barriers ago)
    ++ph;
}

__global__ void __launch_bounds__(NT, 1) rnn_main(
    const float* __restrict__ x,
    const float* __restrict__ lp_w,  const float* __restrict__ lp_b,
    const float* __restrict__ lp_wout, const float* __restrict__ lp_bout,
    const float* __restrict__ w_ih,  const float* __restrict__ b_ih,
    const float* __restrict__ w_hh,  const float* __restrict__ b_hh,
    float* __restrict__ out, int T, int has_l)
{
    __shared__ float  s_a[C];
    __shared__ float  s_b[C];
    __shared__ double s_red[32];
    const int tid  = threadIdx.x;
    const int wid  = tid >> 5;
    const int lane = tid & 31;
    const int m    = wid & 1;          // 0: ih-dot, 1: hh-dot
    const int r    = wid >> 1;         // row within CTA tile
    const int j    = (blockIdx.x << 4) + r;
    unsigned ph = 0;

    // ---------------- LengthProducer: 3 hidden Linear + LeakyReLU(0.2) ----------------
    for (int i = 0; i < 3; i++) {
        const float* vin = (i == 0) ? x : g_lp[(i - 1) & 1];
        stage(s_a, vin, tid);
        __syncthreads();
        if (m == 0) {                   // even warps cover all 2048 rows
            float d = dotLP(lp_w + (size_t)i * C * C + (size_t)j * C, s_a, lane);
            if (lane == 0) {
                float z = __fadd_rn(d, lp_b[i * C + j]);
                g_lp[i & 1][j] = (z >= 0.f) ? z : __fmul_rn(0.2f, z);
            }
        }
        gbar_arrive(); ++ph; gbar_wait(ph * GRID);
    }
    // ---------------- LP output scalar: l = min(|y@wout + bout|, 0.9999) ----------------
    if (blockIdx.x == 0 && wid == 0) {
        float d = dotLP(lp_wout, g_lp[0], lane);
        if (lane == 0 && has_l > 0) {
            float z = __fadd_rn(d, lp_bout[0]);
            out[(size_t)T * C] = fminf(fabsf(z), 0.9999f);
        }
    }
    // prefetch RNN (t=0,l=0) pair 0 and stage its hid operand before arriving
    F8 A0, A1;
    {
        const F8* nb = reinterpret_cast<const F8*>(((m == 0) ? w_ih : w_hh) + (size_t)j * C);
        A0 = ldw8v<0>(nb + lane); A1 = ldw8v<0>(nb + lane + 32);
    }
    gbar_arrive();
    stage(s_b, g_hid[0][0], tid);
    ++ph;

    // ---------------- 4-layer ReLU RNN scan, T steps ----------------
    // L2 policy: w_ih all layers + w_hh layers 0-1 pinned evict_last (96MB);
    // w_hh layers 2-3 streamed evict_first (32MB).
    for (int t = 0; t < T; t++) {
        const int p = t & 1;
        rnn_phase<0,0, 0,0>(0, t, p, 1, p,     j, m, wid, lane, tid, ph,
                            w_ih, w_hh, b_ih, b_hh, out, s_a, s_b, s_red, A0, A1);
        rnn_phase<0,0, 0,1>(1, t, p, 2, p,     j, m, wid, lane, tid, ph,
                            w_ih, w_hh, b_ih, b_hh, out, s_a, s_b, s_red, A0, A1);
        rnn_phase<0,1, 0,1>(2, t, p, 3, p,     j, m, wid, lane, tid, ph,
                            w_ih, w_hh, b_ih, b_hh, out, s_a, s_b, s_red, A0, A1);
        rnn_phase<0,1, 0,0>(3, t, p, 0, p ^ 1, j, m, wid, lane, tid, ph,
                            w_ih, w_hh, b_ih, b_hh, out, s_a, s_b, s_red, A0, A1);
    }
}

extern "C" void kernel_launch(void* const* d_in, const int* in_sizes, int n_in,
                              void* d_out, int out_size) {
    const float* x       = (const float*)d_in[0];
    const float* lp_w    = (const float*)d_in[1];
    const float* lp_b    = (const float*)d_in[2];
    const float* lp_wout = (const float*)d_in[3];
    const float* lp_bout = (const float*)d_in[4];
    const float* w_ih    = (const float*)d_in[5];
    const float* b_ih    = (const float*)d_in[6];
    const float* w_hh    = (const float*)d_in[7];
    const float* b_hh    = (const float*)d_in[8];
    float* out = (float*)d_out;

    int T     = out_size / C;        // 512 seq rows
    int has_l = out_size - T * C;    // trailing scalar l present?

    rnn_init<<<8, 256>>>(x);
    rnn_main<<<GRID, NT>>>(x, lp_w, lp_b, lp_wout, lp_bout,
                           w_ih, b_ih, w_hh, b_hh, out, T, has_l);
}

// round 8
// speedup vs baseline: 1.5148x; 1.0765x over previous
#include <cuda_runtime.h>
#include <math.h>

#define C    2048
#define GRID 148
#define NT   512

typedef unsigned long long ull;

// ---------------- persistent-kernel scratch (device globals; no allocs) ----------------
__device__ __align__(16) float g_inp[C];
__device__ __align__(16) float g_hid[2][4][C];
__device__ __align__(16) float g_hraw[3][C];
__device__ __align__(16) float g_lp[2][C];
__device__ unsigned g_bar;

// ---------------- packed f32x2 primitives (sm_103a FFMA2 path, PTX-only) ----------------
__device__ __forceinline__ ull mul2(ull a, ull b) {
    ull r; asm("mul.rn.f32x2 %0, %1, %2;" : "=l"(r) : "l"(a), "l"(b)); return r;
}
__device__ __forceinline__ ull add2(ull a, ull b) {
    ull r; asm("add.rn.f32x2 %0, %1, %2;" : "=l"(r) : "l"(a), "l"(b)); return r;
}
__device__ __forceinline__ ull fma2(ull a, ull b, ull c) {
    ull r; asm("fma.rn.f32x2 %0, %1, %2, %3;" : "=l"(r) : "l"(a), "l"(b), "l"(c)); return r;
}
__device__ __forceinline__ ull neg2(ull a) { return a ^ 0x8000000080000000ULL; }

// Packed TwoProd+Kahan: two independent scalar chains (lo/hi), identical RN fp32 math.
// nc holds the NEGATED compensation so the hot path is adds. es accumulates product tails.
__device__ __forceinline__ void kaccp(ull a, ull b, ull& s, ull& nc, ull& es) {
    ull p = mul2(a, b);
    ull e = fma2(a, b, neg2(p));       // exact low part of product
    ull y = add2(p, nc);               // y = p - cmp   (nc = -cmp)
    ull t = add2(s, y);
    ull v = add2(s, neg2(t));          // s - t
    nc = add2(v, y);                   // -((t-s)-y)
    s = t;
    es = add2(es, e);
}
// Combine one packed chain set exactly as rounds 1-7: d = s + cmp + es, per component, fp64.
__device__ __forceinline__ double combp(ull s, ull nc, ull es) {
    float slo = __uint_as_float((unsigned)s),  shi = __uint_as_float((unsigned)(s >> 32));
    float clo = -__uint_as_float((unsigned)nc), chi = -__uint_as_float((unsigned)(nc >> 32));
    float elo = __uint_as_float((unsigned)es), ehi = __uint_as_float((unsigned)(es >> 32));
    return ((double)slo + (double)clo + (double)elo)
         + ((double)shi + (double)chi + (double)ehi);
}

// Scalar Kahan (LengthProducer path only; identical to round 1).
__device__ __forceinline__ void kacc(float a, float b, float& s, float& cmp, float& es) {
    float p = __fmul_rn(a, b);
    float e = __fmaf_rn(a, b, -p);
    float y = __fsub_rn(p, cmp);
    float t = __fadd_rn(s, y);
    cmp = __fsub_rn(__fsub_rn(t, s), y);
    s = t;
    es = __fadd_rn(es, e);
}
__device__ __forceinline__ void kacc4(float4 a, float4 b, float& s, float& c, float& e) {
    kacc(a.x, b.x, s, c, e); kacc(a.y, b.y, s, c, e);
    kacc(a.z, b.z, s, c, e); kacc(a.w, b.w, s, c, e);
}

// 256-bit weight chunk, kept packed as 4x b64 (native f32x2 operands).
struct F8 { ull a, b, c, d; };

// POL=0: evict_last (pin ~96MB in L2); POL=1: evict_first (stream w_hh[2..3]).
template<int POL>
__device__ __forceinline__ F8 ldw8(const F8* p) {
    F8 r;
    if (POL == 0)
        asm("ld.global.nc.L2::evict_last.v4.b64 {%0,%1,%2,%3}, [%4];"
            : "=l"(r.a), "=l"(r.b), "=l"(r.c), "=l"(r.d) : "l"(p));
    else
        asm("ld.global.nc.L2::evict_first.v4.b64 {%0,%1,%2,%3}, [%4];"
            : "=l"(r.a), "=l"(r.b), "=l"(r.c), "=l"(r.d) : "l"(p));
    return r;
}
template<int POL>
__device__ __forceinline__ F8 ldw8v(const F8* p) {
    F8 r;
    if (POL == 0)
        asm volatile("ld.global.nc.L2::evict_last.v4.b64 {%0,%1,%2,%3}, [%4];"
            : "=l"(r.a), "=l"(r.b), "=l"(r.c), "=l"(r.d) : "l"(p));
    else
        asm volatile("ld.global.nc.L2::evict_first.v4.b64 {%0,%1,%2,%3}, [%4];"
            : "=l"(r.a), "=l"(r.b), "=l"(r.c), "=l"(r.d) : "l"(p));
    return r;
}

// Split grid barrier. All 148 CTAs co-resident.
__device__ __forceinline__ void gbar_arrive() {
    __syncthreads();
    if (threadIdx.x == 0) {
        __threadfence();
        atomicAdd(&g_bar, 1u);
    }
}
__device__ __forceinline__ void gbar_wait(unsigned target) {
    if (threadIdx.x == 0) {
        unsigned v;
        do {
            asm volatile("ld.global.acquire.gpu.u32 %0, [%1];"
                         : "=r"(v) : "l"(&g_bar) : "memory");
        } while (v < target);
    }
    __syncthreads();
}

__global__ void rnn_init(const float* __restrict__ x) {
    int i = blockIdx.x * blockDim.x + threadIdx.x;
    if (i == 0) g_bar = 0u;
    if (i < C) {
        g_inp[i] = 0.f;
        g_hid[0][0][i] = x[i];
        g_hid[0][1][i] = 0.f;
        g_hid[0][2][i] = 0.f;
        g_hid[0][3][i] = 0.f;
    }
}

// LengthProducer dot (one-shot traffic): scalar Kahan + fp64 reduce, as round 1.
__device__ __forceinline__ float dotLP(const float* __restrict__ wrow,
                                       const float* __restrict__ v, int lane) {
    float s = 0.f, c = 0.f, e = 0.f;
    const float4* w4 = reinterpret_cast<const float4*>(wrow);
    const float4* v4 = reinterpret_cast<const float4*>(v);
#pragma unroll
    for (int i = 0; i < 16; i++) {
        float4 a = __ldg(w4 + lane + 32 * i);
        float4 b = v4[lane + 32 * i];
        kacc4(a, b, s, c, e);
    }
    double d = (double)s + (double)c + (double)e;
#pragma unroll
    for (int o = 16; o > 0; o >>= 1)
        d += __shfl_down_sync(0xffffffffu, d, o);
    return (float)d;
}

// Accumulate one F8 slot (8 elements) against activations (2x ulonglong2 from smem).
__device__ __forceinline__ void accF8(const F8& w, const ulonglong2* v2, int slot,
                                      ull& s, ull& nc, ull& es) {
    ulonglong2 q0 = v2[2 * slot];
    ulonglong2 q1 = v2[2 * slot + 1];
    kaccp(w.a, q0.x, s, nc, es);
    kaccp(w.b, q0.y, s, nc, es);
    kaccp(w.c, q1.x, s, nc, es);
    kaccp(w.d, q1.y, s, nc, es);
}

// One RNN phase (layer l of step t). Round-3 structure: warp owns row j, both dots,
// depth-8 load pipeline. PIH/PHH: this phase's L2 policies; NIH/NHH: next phase's.
template<int PIH, int PHH, int NIH, int NHH>
__device__ __forceinline__ void rnn_phase(
    int l, int t, int p, int nl, int np,
    int j, int lane, int tid, unsigned& ph,
    const float* __restrict__ w_ih, const float* __restrict__ w_hh,
    const float* __restrict__ b_ih, const float* __restrict__ b_hh,
    float* __restrict__ out,
    float* s_a, float* s_b,
    F8& A0, F8& A1, F8& B0, F8& B1)
{
    gbar_wait(ph * GRID);                      // this phase's inputs are now published
    const float* vin = (l == 0) ? g_inp : g_hraw[l - 1];
    reinterpret_cast<float4*>(s_a)[tid] = reinterpret_cast<const float4*>(vin)[tid];
    __syncthreads();

    if (j < C) {
        const F8* wa8 = reinterpret_cast<const F8*>(w_ih + ((size_t)l * C + j) * C);
        const F8* wb8 = reinterpret_cast<const F8*>(w_hh + ((size_t)l * C + j) * C);
        const ulonglong2* a2 = reinterpret_cast<const ulonglong2*>(s_a);
        const ulonglong2* b2 = reinterpret_cast<const ulonglong2*>(s_b);
        ull sa = 0, nca = 0, esa = 0;          // packed chain set, ih-dot
        ull sb = 0, ncb = 0, esb = 0;          // packed chain set, hh-dot
        F8 x0 = A0, x1 = A1, y0 = B0, y1 = B1;
#pragma unroll
        for (int ch = 0; ch < 4; ch++) {
            F8 n0, n1, m0, m1;
            if (ch < 3) {                       // stream chunk ch+1 while computing chunk ch
                int o = lane + 64 * (ch + 1);
                n0 = ldw8<PIH>(wa8 + o); n1 = ldw8<PIH>(wa8 + o + 32);
                m0 = ldw8<PHH>(wb8 + o); m1 = ldw8<PHH>(wb8 + o + 32);
            }
            int e = lane + 64 * ch;
            accF8(x0, a2, e,      sa, nca, esa);
            accF8(x1, a2, e + 32, sa, nca, esa);
            accF8(y0, b2, e,      sb, ncb, esb);
            accF8(y1, b2, e + 32, sb, ncb, esb);
            if (ch < 3) { x0 = n0; x1 = n1; y0 = m0; y1 = m1; }
        }
        double da = combp(sa, nca, esa);
        double db = combp(sb, ncb, esb);
#pragma unroll
        for (int o = 16; o > 0; o >>= 1) {
            da += __shfl_down_sync(0xffffffffu, da, o);
            db += __shfl_down_sync(0xffffffffu, db, o);
        }
        if (lane == 0) {
            // ref rounding: ((dih + b_ih) + dhh) + b_hh, all fp32 RN
            float pre = __fadd_rn(__fadd_rn(__fadd_rn((float)da, b_ih[l * C + j]),
                                            (float)db), b_hh[l * C + j]);
            float h  = fmaxf(pre, 0.f);
            float n  = __fsqrt_rn(__fmul_rn(h, h));
            float hn = __fdiv_rn(h, __fadd_rn(n, 1e-12f));
            g_hid[p ^ 1][l][j] = hn;
            if (l < 3) g_hraw[l][j] = h;
            else { g_inp[j] = hn; out[(size_t)t * C + j] = hn; }
        }
    }

    // ---- tail: prefetch next phase's chunk 0 (overlaps barrier), arrive, stage s_b ----
    if (j < C) {
        const F8* na = reinterpret_cast<const F8*>(w_ih + ((size_t)nl * C + j) * C);
        const F8* nb = reinterpret_cast<const F8*>(w_hh + ((size_t)nl * C + j) * C);
        A0 = ldw8v<NIH>(na + lane); A1 = ldw8v<NIH>(na + lane + 32);
        B0 = ldw8v<NHH>(nb + lane); B1 = ldw8v<NHH>(nb + lane + 32);
    }
    gbar_arrive();
    // next phase's hid operand has been stable for >=3 barriers: stage pre-wait
    reinterpret_cast<float4*>(s_b)[tid] =
        reinterpret_cast<const float4*>(g_hid[np][nl])[tid];
    ++ph;
}

__global__ void __launch_bounds__(NT, 1) rnn_main(
    const float* __restrict__ x,
    const float* __restrict__ lp_w,  const float* __restrict__ lp_b,
    const float* __restrict__ lp_wout, const float* __restrict__ lp_bout,
    const float* __restrict__ w_ih,  const float* __restrict__ b_ih,
    const float* __restrict__ w_hh,  const float* __restrict__ b_hh,
    float* __restrict__ out, int T, int has_l)
{
    __shared__ float s_a[C];
    __shared__ float s_b[C];
    const int tid  = threadIdx.x;
    const int w    = tid >> 5;
    const int lane = tid & 31;
    const int bid  = blockIdx.x;
    const int j    = w * GRID + bid;
    unsigned ph = 0;

    // ---------------- LengthProducer: 3 hidden Linear + LeakyReLU(0.2) ----------------
    for (int i = 0; i < 3; i++) {
        const float* vin = (i == 0) ? x : g_lp[(i - 1) & 1];
        reinterpret_cast<float4*>(s_a)[tid] = reinterpret_cast<const float4*>(vin)[tid];
        __syncthreads();
        if (j < C) {
            float d = dotLP(lp_w + (size_t)i * C * C + (size_t)j * C, s_a, lane);
            if (lane == 0) {
                float z = __fadd_rn(d, lp_b[i * C + j]);
                g_lp[i & 1][j] = (z >= 0.f) ? z : __fmul_rn(0.2f, z);
            }
        }
        gbar_arrive(); ++ph; gbar_wait(ph * GRID);
    }
    // ---------------- LP output scalar: l = min(|y@wout + bout|, 0.9999) ----------------
    if (bid == 0 && w == 0) {
        float d = dotLP(lp_wout, g_lp[0], lane);
        if (lane == 0 && has_l > 0) {
            float z = __fadd_rn(d, lp_bout[0]);
            out[(size_t)T * C] = fminf(fabsf(z), 0.9999f);
        }
    }
    // prefetch RNN phase (t=0, l=0) chunk 0 and stage its hid operand before arriving
    F8 A0, A1, B0, B1;
    if (j < C) {
        const F8* na = reinterpret_cast<const F8*>(w_ih + (size_t)j * C);
        const F8* nb = reinterpret_cast<const F8*>(w_hh + (size_t)j * C);
        A0 = ldw8v<0>(na + lane); A1 = ldw8v<0>(na + lane + 32);
        B0 = ldw8v<0>(nb + lane); B1 = ldw8v<0>(nb + lane + 32);
    }
    gbar_arrive();
    reinterpret_cast<float4*>(s_b)[tid] = reinterpret_cast<const float4*>(g_hid[0][0])[tid];
    ++ph;

    // ---------------- 4-layer ReLU RNN scan, T steps ----------------
    // L2 policy: w_ih all layers + w_hh layers 0-1 pinned evict_last (96MB);
    // w_hh layers 2-3 streamed evict_first (32MB).
    for (int t = 0; t < T; t++) {
        const int p = t & 1;
        rnn_phase<0,0, 0,0>(0, t, p, 1, p,     j, lane, tid, ph, w_ih, w_hh, b_ih, b_hh,
                            out, s_a, s_b, A0, A1, B0, B1);
        rnn_phase<0,0, 0,1>(1, t, p, 2, p,     j, lane, tid, ph, w_ih, w_hh, b_ih, b_hh,
                            out, s_a, s_b, A0, A1, B0, B1);
        rnn_phase<0,1, 0,1>(2, t, p, 3, p,     j, lane, tid, ph, w_ih, w_hh, b_ih, b_hh,
                            out, s_a, s_b, A0, A1, B0, B1);
        rnn_phase<0,1, 0,0>(3, t, p, 0, p ^ 1, j, lane, tid, ph, w_ih, w_hh, b_ih, b_hh,
                            out, s_a, s_b, A0, A1, B0, B1);
    }
}

extern "C" void kernel_launch(void* const* d_in, const int* in_sizes, int n_in,
                              void* d_out, int out_size) {
    const float* x       = (const float*)d_in[0];
    const float* lp_w    = (const float*)d_in[1];
    const float* lp_b    = (const float*)d_in[2];
    const float* lp_wout = (const float*)d_in[3];
    const float* lp_bout = (const float*)d_in[4];
    const float* w_ih    = (const float*)d_in[5];
    const float* b_ih    = (const float*)d_in[6];
    const float* w_hh    = (const float*)d_in[7];
    const float* b_hh    = (const float*)d_in[8];
    float* out = (float*)d_out;

    int T     = out_size / C;        // 512 seq rows
    int has_l = out_size - T * C;    // trailing scalar l present?

    rnn_init<<<8, 256>>>(x);
    rnn_main<<<GRID, NT>>>(x, lp_w, lp_b, lp_wout, lp_bout,
                           w_ih, b_ih, w_hh, b_hh, out, T, has_l);
}

// round 9
// speedup vs baseline: 1.7619x; 1.1631x over previous
#include <cuda_runtime.h>
#include <math.h>

#define C    2048
#define GRID 148
#define NT   512
// dynamic smem: s_a(2048) + s_b(2048) + hh2 cache(14*2048) + hh3 cache(8*2048) floats
#define SMEM_FLOATS (2*C + 14*C + 8*C)
#define SMEM_BYTES  (SMEM_FLOATS * 4)

// ---------------- persistent-kernel scratch (device globals; no allocs) ----------------
__device__ __align__(16) float g_inp[C];
__device__ __align__(16) float g_hid[2][4][C];
__device__ __align__(16) float g_hraw[3][C];
__device__ __align__(16) float g_lp[2][C];
__device__ unsigned g_bar;

// Near-exact compensated accumulation: TwoProd (FMA) + Kahan, all RN intrinsics.
__device__ __forceinline__ void kacc(float a, float b, float& s, float& cmp, float& es) {
    float p = __fmul_rn(a, b);
    float e = __fmaf_rn(a, b, -p);
    float y = __fsub_rn(p, cmp);
    float t = __fadd_rn(s, y);
    cmp = __fsub_rn(__fsub_rn(t, s), y);
    s = t;
    es = __fadd_rn(es, e);
}
__device__ __forceinline__ void kacc4(float4 a, float4 b, float& s, float& c, float& e) {
    kacc(a.x, b.x, s, c, e); kacc(a.y, b.y, s, c, e);
    kacc(a.z, b.z, s, c, e); kacc(a.w, b.w, s, c, e);
}

// 256-bit (8-float) weight chunk; sm_103a needs v4.b64 width for L2 evict hints.
struct F8 { float4 lo, hi; };

__device__ __forceinline__ F8 unpack8(unsigned long long a, unsigned long long b,
                                      unsigned long long c, unsigned long long d) {
    F8 r;
    r.lo.x = __uint_as_float((unsigned)a); r.lo.y = __uint_as_float((unsigned)(a >> 32));
    r.lo.z = __uint_as_float((unsigned)b); r.lo.w = __uint_as_float((unsigned)(b >> 32));
    r.hi.x = __uint_as_float((unsigned)c); r.hi.y = __uint_as_float((unsigned)(c >> 32));
    r.hi.z = __uint_as_float((unsigned)d); r.hi.w = __uint_as_float((unsigned)(d >> 32));
    return r;
}

// POL=0: evict_last (global weight set now ~103MB, fits L2); POL=1: evict_first (one-shot).
template<int POL>
__device__ __forceinline__ F8 ldw8(const F8* p) {
    unsigned long long a, b, c, d;
    if (POL == 0)
        asm("ld.global.nc.L2::evict_last.v4.b64 {%0,%1,%2,%3}, [%4];"
            : "=l"(a), "=l"(b), "=l"(c), "=l"(d) : "l"(p));
    else
        asm("ld.global.nc.L2::evict_first.v4.b64 {%0,%1,%2,%3}, [%4];"
            : "=l"(a), "=l"(b), "=l"(c), "=l"(d) : "l"(p));
    return unpack8(a, b, c, d);
}
template<int POL>
__device__ __forceinline__ F8 ldw8v(const F8* p) {
    unsigned long long a, b, c, d;
    if (POL == 0)
        asm volatile("ld.global.nc.L2::evict_last.v4.b64 {%0,%1,%2,%3}, [%4];"
            : "=l"(a), "=l"(b), "=l"(c), "=l"(d) : "l"(p));
    else
        asm volatile("ld.global.nc.L2::evict_first.v4.b64 {%0,%1,%2,%3}, [%4];"
            : "=l"(a), "=l"(b), "=l"(c), "=l"(d) : "l"(p));
    return unpack8(a, b, c, d);
}

// Split grid barrier. All 148 CTAs co-resident (1 per SM at 192KB smem).
__device__ __forceinline__ void gbar_arrive() {
    __syncthreads();
    if (threadIdx.x == 0) {
        __threadfence();
        atomicAdd(&g_bar, 1u);
    }
}
__device__ __forceinline__ void gbar_wait(unsigned target) {
    if (threadIdx.x == 0) {
        unsigned v;
        do {
            asm volatile("ld.global.acquire.gpu.u32 %0, [%1];"
                         : "=r"(v) : "l"(&g_bar) : "memory");
        } while (v < target);
    }
    __syncthreads();
}

__global__ void rnn_init(const float* __restrict__ x) {
    int i = blockIdx.x * blockDim.x + threadIdx.x;
    if (i == 0) g_bar = 0u;
    if (i < C) {
        g_inp[i] = 0.f;
        g_hid[0][0][i] = x[i];
        g_hid[0][1][i] = 0.f;
        g_hid[0][2][i] = 0.f;
        g_hid[0][3][i] = 0.f;
    }
}

// LengthProducer dot (one-shot traffic): scalar Kahan + fp64 reduce.
__device__ __forceinline__ float dotLP(const float* __restrict__ wrow,
                                       const float* __restrict__ v, int lane) {
    float s = 0.f, c = 0.f, e = 0.f;
    const float4* w4 = reinterpret_cast<const float4*>(wrow);
    const float4* v4 = reinterpret_cast<const float4*>(v);
#pragma unroll
    for (int i = 0; i < 16; i++) {
        float4 a = __ldg(w4 + lane + 32 * i);
        float4 b = v4[lane + 32 * i];
        kacc4(a, b, s, c, e);
    }
    double d = (double)s + (double)c + (double)e;
#pragma unroll
    for (int o = 16; o > 0; o >>= 1)
        d += __shfl_down_sync(0xffffffffu, d, o);
    return (float)d;
}

// Dual global dot (round-3 proven path): ih + hh pipelined, depth-8 LDG.256.
__device__ __forceinline__ void dot_dual(const F8* __restrict__ wa8,
                                         const F8* __restrict__ wb8,
                                         const float4* a4, const float4* b4, int lane,
                                         F8 A0, F8 A1, F8 B0, F8 B1,
                                         double& da, double& db) {
    float sa = 0.f, ca = 0.f, ea = 0.f, sb = 0.f, cb = 0.f, eb = 0.f;
    F8 x0 = A0, x1 = A1, y0 = B0, y1 = B1;
#pragma unroll
    for (int ch = 0; ch < 4; ch++) {
        F8 n0, n1, m0, m1;
        if (ch < 3) {
            int o = lane + 64 * (ch + 1);
            n0 = ldw8<0>(wa8 + o); n1 = ldw8<0>(wa8 + o + 32);
            m0 = ldw8<0>(wb8 + o); m1 = ldw8<0>(wb8 + o + 32);
        }
        int e = lane + 64 * ch;
        kacc4(x0.lo, a4[2 * e],            sa, ca, ea);
        kacc4(x0.hi, a4[2 * e + 1],        sa, ca, ea);
        kacc4(x1.lo, a4[2 * (e + 32)],     sa, ca, ea);
        kacc4(x1.hi, a4[2 * (e + 32) + 1], sa, ca, ea);
        kacc4(y0.lo, b4[2 * e],            sb, cb, eb);
        kacc4(y0.hi, b4[2 * e + 1],        sb, cb, eb);
        kacc4(y1.lo, b4[2 * (e + 32)],     sb, cb, eb);
        kacc4(y1.hi, b4[2 * (e + 32) + 1], sb, cb, eb);
        if (ch < 3) { x0 = n0; x1 = n1; y0 = m0; y1 = m1; }
    }
    da = (double)sa + ca + ea;
    db = (double)sb + cb + eb;
}

// Single global (ih) pipelined dot.
__device__ __forceinline__ double dot_ih(const F8* __restrict__ wa8,
                                         const float4* a4, int lane, F8 A0, F8 A1) {
    float s = 0.f, c = 0.f, e = 0.f;
    F8 x0 = A0, x1 = A1;
#pragma unroll
    for (int ch = 0; ch < 4; ch++) {
        F8 n0, n1;
        if (ch < 3) {
            int o = lane + 64 * (ch + 1);
            n0 = ldw8<0>(wa8 + o); n1 = ldw8<0>(wa8 + o + 32);
        }
        int t = lane + 64 * ch;
        kacc4(x0.lo, a4[2 * t],            s, c, e);
        kacc4(x0.hi, a4[2 * t + 1],        s, c, e);
        kacc4(x1.lo, a4[2 * (t + 32)],     s, c, e);
        kacc4(x1.hi, a4[2 * (t + 32) + 1], s, c, e);
        if (ch < 3) { x0 = n0; x1 = n1; }
    }
    return (double)s + c + e;
}

// hh dot from the per-CTA smem weight cache (same accumulation order).
__device__ __forceinline__ double dot_smem(const float4* __restrict__ w4,
                                           const float4* b4, int lane) {
    float s = 0.f, c = 0.f, e = 0.f;
#pragma unroll
    for (int ch = 0; ch < 4; ch++) {
        int t = lane + 64 * ch;
        kacc4(w4[2 * t],            b4[2 * t],            s, c, e);
        kacc4(w4[2 * t + 1],        b4[2 * t + 1],        s, c, e);
        kacc4(w4[2 * (t + 32)],     b4[2 * (t + 32)],     s, c, e);
        kacc4(w4[2 * (t + 32) + 1], b4[2 * (t + 32) + 1], s, c, e);
    }
    return (double)s + c + e;
}

// One RNN phase. HH: 0 = hh from global, 1 = hh from s_hh2, 2 = smem if w<8 else global.
// NB: prefetch next phase's hh chunk0? 0 = no, 1 = yes, 2 = only w>=8.
template<int HH, int NB>
__device__ __forceinline__ void rnn_phase(
    int l, int t, int p, int nl, int np,
    int j, int w, int lane, int tid, unsigned& ph,
    const float* __restrict__ w_ih, const float* __restrict__ w_hh,
    const float* __restrict__ b_ih, const float* __restrict__ b_hh,
    float* __restrict__ out,
    float* s_a, float* s_b, const float* s_hh2, const float* s_hh3,
    F8& A0, F8& A1, F8& B0, F8& B1)
{
    gbar_wait(ph * GRID);                      // this phase's inputs are now published
    const float* vin = (l == 0) ? g_inp : g_hraw[l - 1];
    reinterpret_cast<float4*>(s_a)[tid] = reinterpret_cast<const float4*>(vin)[tid];
    __syncthreads();

    if (j < C) {
        const F8* wa8 = reinterpret_cast<const F8*>(w_ih + ((size_t)l * C + j) * C);
        const float4* a4 = reinterpret_cast<const float4*>(s_a);
        const float4* b4 = reinterpret_cast<const float4*>(s_b);
        double da, db;
        if (HH == 0 || (HH == 2 && w >= 8)) {
            const F8* wb8 = reinterpret_cast<const F8*>(w_hh + ((size_t)l * C + j) * C);
            dot_dual(wa8, wb8, a4, b4, lane, A0, A1, B0, B1, da, db);
        } else {
            const float* srow = (HH == 1) ? (s_hh2 + w * C) : (s_hh3 + w * C);
            da = dot_ih(wa8, a4, lane, A0, A1);
            db = dot_smem(reinterpret_cast<const float4*>(srow), b4, lane);
        }
#pragma unroll
        for (int o = 16; o > 0; o >>= 1) {
            da += __shfl_down_sync(0xffffffffu, da, o);
            db += __shfl_down_sync(0xffffffffu, db, o);
        }
        if (lane == 0) {
            // ref rounding: ((dih + b_ih) + dhh) + b_hh, all fp32 RN
            float pre = __fadd_rn(__fadd_rn(__fadd_rn((float)da, b_ih[l * C + j]),
                                            (float)db), b_hh[l * C + j]);
            float h  = fmaxf(pre, 0.f);
            float n  = __fsqrt_rn(__fmul_rn(h, h));
            float hn = __fdiv_rn(h, __fadd_rn(n, 1e-12f));
            g_hid[p ^ 1][l][j] = hn;
            if (l < 3) g_hraw[l][j] = h;
            else { g_inp[j] = hn; out[(size_t)t * C + j] = hn; }
        }
    }

    // ---- tail: prefetch next phase's chunk 0 (overlaps barrier), arrive, stage s_b ----
    if (j < C) {
        const F8* na = reinterpret_cast<const F8*>(w_ih + ((size_t)nl * C + j) * C);
        A0 = ldw8v<0>(na + lane); A1 = ldw8v<0>(na + lane + 32);
        if (NB == 1 || (NB == 2 && w >= 8)) {
            const F8* nb = reinterpret_cast<const F8*>(w_hh + ((size_t)nl * C + j) * C);
            B0 = ldw8v<0>(nb + lane); B1 = ldw8v<0>(nb + lane + 32);
        }
    }
    gbar_arrive();
    // next phase's hid operand has been stable for >=3 barriers: stage pre-wait
    reinterpret_cast<float4*>(s_b)[tid] =
        reinterpret_cast<const float4*>(g_hid[np][nl])[tid];
    ++ph;
}

__global__ void __launch_bounds__(NT, 1) rnn_main(
    const float* __restrict__ x,
    const float* __restrict__ lp_w,  const float* __restrict__ lp_b,
    const float* __restrict__ lp_wout, const float* __restrict__ lp_bout,
    const float* __restrict__ w_ih,  const float* __restrict__ b_ih,
    const float* __restrict__ w_hh,  const float* __restrict__ b_hh,
    float* __restrict__ out, int T, int has_l)
{
    extern __shared__ float dsm[];
    float* s_a   = dsm;                 // 2048
    float* s_b   = dsm + C;             // 2048
    float* s_hh2 = dsm + 2 * C;         // 14 rows: warp w's row of w_hh[2]
    float* s_hh3 = dsm + 2 * C + 14 * C;// 8 rows:  warps 0-7's row of w_hh[3]

    const int tid  = threadIdx.x;
    const int w    = tid >> 5;
    const int lane = tid & 31;
    const int bid  = blockIdx.x;
    const int j    = w * GRID + bid;
    unsigned ph = 0;

    // ---------------- fill per-CTA smem weight cache (one-time; evict_first loads) ----------------
    if (j < C) {
        const F8* src2 = reinterpret_cast<const F8*>(w_hh + ((size_t)2 * C + j) * C);
        float4* dst2 = reinterpret_cast<float4*>(s_hh2 + w * C);
        for (int i = lane; i < C / 8; i += 32) {
            F8 v = ldw8<1>(src2 + i);
            dst2[2 * i] = v.lo; dst2[2 * i + 1] = v.hi;
        }
        if (w < 8) {
            const F8* src3 = reinterpret_cast<const F8*>(w_hh + ((size_t)3 * C + j) * C);
            float4* dst3 = reinterpret_cast<float4*>(s_hh3 + w * C);
            for (int i = lane; i < C / 8; i += 32) {
                F8 v = ldw8<1>(src3 + i);
                dst3[2 * i] = v.lo; dst3[2 * i + 1] = v.hi;
            }
        }
    }
    __syncthreads();

    // ---------------- LengthProducer: 3 hidden Linear + LeakyReLU(0.2) ----------------
    for (int i = 0; i < 3; i++) {
        const float* vin = (i == 0) ? x : g_lp[(i - 1) & 1];
        reinterpret_cast<float4*>(s_a)[tid] = reinterpret_cast<const float4*>(vin)[tid];
        __syncthreads();
        if (j < C) {
            float d = dotLP(lp_w + (size_t)i * C * C + (size_t)j * C, s_a, lane);
            if (lane == 0) {
                float z = __fadd_rn(d, lp_b[i * C + j]);
                g_lp[i & 1][j] = (z >= 0.f) ? z : __fmul_rn(0.2f, z);
            }
        }
        gbar_arrive(); ++ph; gbar_wait(ph * GRID);
    }
    // ---------------- LP output scalar: l = min(|y@wout + bout|, 0.9999) ----------------
    if (bid == 0 && w == 0) {
        float d = dotLP(lp_wout, g_lp[0], lane);
        if (lane == 0 && has_l > 0) {
            float z = __fadd_rn(d, lp_bout[0]);
            out[(size_t)T * C] = fminf(fabsf(z), 0.9999f);
        }
    }
    // prefetch RNN (t=0,l=0) chunk 0 and stage its hid operand before arriving
    F8 A0, A1, B0, B1;
    if (j < C) {
        const F8* na = reinterpret_cast<const F8*>(w_ih + (size_t)j * C);
        const F8* nb = reinterpret_cast<const F8*>(w_hh + (size_t)j * C);
        A0 = ldw8v<0>(na + lane); A1 = ldw8v<0>(na + lane + 32);
        B0 = ldw8v<0>(nb + lane); B1 = ldw8v<0>(nb + lane + 32);
    }
    gbar_arrive();
    reinterpret_cast<float4*>(s_b)[tid] = reinterpret_cast<const float4*>(g_hid[0][0])[tid];
    ++ph;

    // ---------------- 4-layer ReLU RNN scan, T steps ----------------
    // hh2 fully smem-cached; hh3 smem-cached for warps 0-7. Remaining global set
    // (~103MB) pinned evict_last -> fits L2.
    for (int t = 0; t < T; t++) {
        const int p = t & 1;
        rnn_phase<0,1>(0, t, p, 1, p,     j, w, lane, tid, ph, w_ih, w_hh, b_ih, b_hh,
                       out, s_a, s_b, s_hh2, s_hh3, A0, A1, B0, B1);
        rnn_phase<0,0>(1, t, p, 2, p,     j, w, lane, tid, ph, w_ih, w_hh, b_ih, b_hh,
                       out, s_a, s_b, s_hh2, s_hh3, A0, A1, B0, B1);
        rnn_phase<1,2>(2, t, p, 3, p,     j, w, lane, tid, ph, w_ih, w_hh, b_ih, b_hh,
                       out, s_a, s_b, s_hh2, s_hh3, A0, A1, B0, B1);
        rnn_phase<2,1>(3, t, p, 0, p ^ 1, j, w, lane, tid, ph, w_ih, w_hh, b_ih, b_hh,
                       out, s_a, s_b, s_hh2, s_hh3, A0, A1, B0, B1);
    }
}

extern "C" void kernel_launch(void* const* d_in, const int* in_sizes, int n_in,
                              void* d_out, int out_size) {
    const float* x       = (const float*)d_in[0];
    const float* lp_w    = (const float*)d_in[1];
    const float* lp_b    = (const float*)d_in[2];
    const float* lp_wout = (const float*)d_in[3];
    const float* lp_bout = (const float*)d_in[4];
    const float* w_ih    = (const float*)d_in[5];
    const float* b_ih    = (const float*)d_in[6];
    const float* w_hh    = (const float*)d_in[7];
    const float* b_hh    = (const float*)d_in[8];
    float* out = (float*)d_out;

    int T     = out_size / C;        // 512 seq rows
    int has_l = out_size - T * C;    // trailing scalar l present?

    cudaFuncSetAttribute(rnn_main, cudaFuncAttributeMaxDynamicSharedMemorySize, SMEM_BYTES);

    rnn_init<<<8, 256>>>(x);
    rnn_main<<<GRID, NT, SMEM_BYTES>>>(x, lp_w, lp_b, lp_wout, lp_bout,
                                       w_ih, b_ih, w_hh, b_hh, out, T, has_l);
}